// round 15
// baseline (speedup 1.0000x reference)
#include <cuda_runtime.h>

#define NN 100000
#define EE 1600000
#define BUCKET 96        // fixed slots per node (Poisson(16): P(deg>96) ~ e^-40)
#define SCAP 64          // per-warp smem-staged edge cap (P(deg>64) ~ 2e-13)

// ---------------- scratch (static device globals; no allocation) ------------
__device__ float  g_h[NN * 128];          // node features, updated in place
__device__ float2 g_hblkA[NN * 32];       // ping-pong relu(LN(half)) buffers
__device__ float2 g_hblkB[NN * 32];
__device__ int    g_cnt[NN];              // degree; zero-init; re-zeroed by k_gen ph3
__device__ int    g_srcp[NN * BUCKET];    // src bucketed by dst
__device__ float  g_eap[NN * BUCKET * 8]; // edge_attr bucketed by dst (307MB)
__device__ float  g_wc[4 * 8 * 64];       // folded W_ee @ We per block
__device__ float  g_bc[4 * 64];           // folded bias per block
__device__ int    g_gen;                  // grid-barrier generation (monotonic)
__device__ int    g_count;                // grid-barrier counter (resets to 0)

#define GRID_BARRIER(k)                                                       \
    __syncthreads();                                                          \
    if (tid == 0) {                                                           \
        __threadfence();                                                      \
        int t_ = atomicAdd(&g_count, 1);                                      \
        if (t_ == nblk - 1) {                                                 \
            atomicExch(&g_count, 0);                                          \
            __threadfence();                                                  \
            atomicAdd(&g_gen, 1);                                             \
        } else {                                                              \
            while (*(volatile int*)&g_gen < s_gen_entry + (k) + 1)            \
                __nanosleep(64);                                              \
        }                                                                     \
        __threadfence();                                                      \
    }                                                                         \
    __syncthreads();

// ===== prep: wc | encode(+LN0) | direct bucket scatter — single phase ========
// No barriers; tasks independent. Alternating task order per block overlaps
// latency-bound scatter with compute-bound encode across co-resident blocks.
// launch_bounds(256,4): 64-reg cap -> 4 blocks/SM (R14 ran at 1 block/SM!).
__global__ void __launch_bounds__(256, 4) k_prep_all(
        const int* __restrict__ src, const int* __restrict__ dst,
        const float4* __restrict__ ea,
        const float* __restrict__ x, const int* __restrict__ nidx,
        const float* __restrict__ nodef,
        const float* __restrict__ Woh, const float* __restrict__ boh,
        const float* __restrict__ Wne, const float* __restrict__ bne,
        const float* __restrict__ ln0g, const float* __restrict__ ln0b,
        const float* __restrict__ Wee, const float* __restrict__ bee,
        const float* __restrict__ We, const float* __restrict__ be) {
    __shared__ float s_woh[64], s_boh[8], s_wne[2048], s_bne[128];
    int tid = threadIdx.x, lane = tid & 31, wid = tid >> 5;
    int nblk = gridDim.x, b = blockIdx.x;
    int gw = b * 8 + wid;

    // ---- wc: warp per output (2304 outputs), tiny ----
    for (int idx = gw; idx < 2304; idx += nblk * 8) {
        if (idx < 2048) {
            int bb = idx >> 9, k = (idx >> 6) & 7, c = idx & 63;
            float s = 0.f;
            for (int j = lane; j < 128; j += 32)
                s += Wee[k * 128 + j] * We[(bb * 128 + j) * 64 + c];
            #pragma unroll
            for (int d = 16; d > 0; d >>= 1) s += __shfl_xor_sync(0xffffffffu, s, d);
            if (lane == 0) g_wc[idx] = s;
        } else {
            int i2 = idx - 2048;
            int bb = i2 >> 6, c = i2 & 63;
            float s = 0.f;
            for (int j = lane; j < 128; j += 32)
                s += bee[j] * We[(bb * 128 + j) * 64 + c];
            #pragma unroll
            for (int d = 16; d > 0; d >>= 1) s += __shfl_xor_sync(0xffffffffu, s, d);
            if (lane == 0) g_bc[i2] = be[i2] + s;
        }
    }
    // stage encoder weights
    for (int i = tid; i < 64; i += 256) s_woh[i] = Woh[i];
    for (int i = tid; i < 8; i += 256) s_boh[i] = boh[i];
    for (int i = tid; i < 2048; i += 256) s_wne[i] = Wne[i];
    for (int i = tid; i < 128; i += 256) s_bne[i] = bne[i];
    __syncthreads();

    for (int half = 0; half < 2; half++) {
        // even blocks: scatter then encode; odd blocks: encode then scatter
        if ((half ^ (b & 1)) == 0) {
            // ---- scatter into fixed-stride buckets ----
            float4* o = (float4*)g_eap;
            for (int i = b * 256 + tid; i < EE; i += nblk * 256) {
                int d = dst[i];
                int pos = atomicAdd(&g_cnt[d], 1);
                int p = d * BUCKET + pos;
                g_srcp[p] = src[i];
                o[p * 2]     = __ldg(&ea[i * 2]);
                o[p * 2 + 1] = __ldg(&ea[i * 2 + 1]);
            }
        } else {
            // ---- encode + fused LN/relu block 0 -> hblkA ----
            for (int n = gw; n < NN; n += nblk * 8) {
                int s = nidx[n];
                float4 a  = *(const float4*)(nodef + s * 8);
                float4 b4 = *(const float4*)(nodef + s * 8 + 4);
                float nf1[8] = {a.x, a.y, a.z, a.w, b4.x, b4.y, b4.z, b4.w};
                float4 xa = *(const float4*)(x + n * 8);
                float4 xb = *(const float4*)(x + n * 8 + 4);
                float xv[8] = {xa.x, xa.y, xa.z, xa.w, xb.x, xb.y, xb.z, xb.w};
                float nf2[8];
                #pragma unroll
                for (int j = 0; j < 8; j++) {
                    float t = s_boh[j];
                    #pragma unroll
                    for (int i = 0; i < 8; i++) t += xv[i] * s_woh[i * 8 + j];
                    nf2[j] = t;
                }
                float acc[4];
                #pragma unroll
                for (int cc = 0; cc < 4; cc++) {
                    int c = lane + cc * 32;
                    float t = s_bne[c];
                    #pragma unroll
                    for (int k = 0; k < 8; k++) t += nf1[k] * s_wne[k * 128 + c];
                    #pragma unroll
                    for (int k = 0; k < 8; k++) t += nf2[k] * s_wne[(8 + k) * 128 + c];
                    g_h[n * 128 + c] = t;
                    acc[cc] = t;
                }
                float v0 = acc[2], v1 = acc[3];
                float su = v0 + v1, q = v0 * v0 + v1 * v1;
                #pragma unroll
                for (int d = 16; d > 0; d >>= 1) {
                    su += __shfl_xor_sync(0xffffffffu, su, d);
                    q  += __shfl_xor_sync(0xffffffffu, q, d);
                }
                float mu = su * (1.f / 64.f);
                float rs = rsqrtf(q * (1.f / 64.f) - mu * mu + 1e-5f);
                float r0 = fmaxf((v0 - mu) * rs * ln0g[lane] + ln0b[lane], 0.f);
                float r1 = fmaxf((v1 - mu) * rs * ln0g[lane + 32] + ln0b[lane + 32], 0.f);
                g_hblkA[n * 32 + lane] = make_float2(r0, r1);
            }
        }
    }
}

// ----- persistent 4-phase GEN: warp-independent, per-warp smem staging ------
// Each warp owns a node stream; stages its node's edges (<=SCAP) into its own
// smem slice (__syncwarp only). Depth-3 pipeline on the hblk gather.
// Unshifted softmax (exact: msg bounded; weights invariant to shift/+eps;
// agg = sum(relu*w) + eps, guarded so empty nodes stay exactly 0).
// Phase 3 zeroes g_cnt[node] after its last read (replay-invariant state).
__global__ void __launch_bounds__(256, 4) k_gen(
        const float* __restrict__ Wm, const float* __restrict__ bm,
        const float* __restrict__ lng, const float* __restrict__ lnb) {
    __shared__ float wms[4096];             // paired: (w[k][c], w[k][c+32])
    __shared__ float4 s_eap[8 * SCAP * 2];  // 16KB, per-warp slices
    __shared__ int s_src[8 * SCAP];         // 2KB
    __shared__ int s_gen_entry;
    int tid = threadIdx.x;
    int lane = tid & 31, wid = tid >> 5;
    if (tid == 0) s_gen_entry = *(volatile int*)&g_gen;
    int nblk = gridDim.x;
    int gwarp = blockIdx.x * 8 + wid;
    int nwarp = nblk * 8;
    const float4* eap = (const float4*)g_eap;
    float4* my_eap = s_eap + wid * SCAP * 2;
    int* my_src = s_src + wid * SCAP;

    for (int phase = 0; phase < 4; phase++) {
        __syncthreads();
        for (int i = tid; i < 4096; i += 256) {
            int k = i >> 6, c = i & 63;
            int col = (c >> 1) + ((c & 1) << 5);
            wms[i] = Wm[phase * 4096 + k * 64 + col];
        }
        __syncthreads();
        const float2* __restrict__ hin = (phase & 1) ? g_hblkB : g_hblkA;
        float2* __restrict__ hout = (phase & 1) ? g_hblkA : g_hblkB;
        int outoff = (phase & 1) ? 64 : 0;
        const float* ng = (phase < 3) ? (lng + (phase + 1) * 64) : (const float*)0;
        const float* nb = (phase < 3) ? (lnb + (phase + 1) * 64) : (const float*)0;
        const float* Wc = g_wc + phase * 512;
        float wA[8], wB[8];
        #pragma unroll
        for (int k = 0; k < 8; k++) {
            wA[k] = __ldg(&Wc[k * 64 + lane]);
            wB[k] = __ldg(&Wc[k * 64 + lane + 32]);
        }
        float bc0 = __ldg(&g_bc[phase * 64 + lane]);
        float bc1 = __ldg(&g_bc[phase * 64 + lane + 32]);
        float bm0 = __ldg(&bm[phase * 64 + lane]);
        float bm1 = __ldg(&bm[phase * 64 + lane + 32]);

        for (int node = gwarp; node < NN; node += nwarp) {
            int cnt = *(volatile int*)&g_cnt[node];
            int base = node * BUCKET;
            int staged = min(cnt, SCAP);
            // per-warp staging, warp-local sync only
            for (int j = lane; j < staged; j += 32) {
                my_src[j] = __ldg(&g_srcp[base + j]);
                my_eap[j * 2]     = __ldg(&eap[(base + j) * 2]);
                my_eap[j * 2 + 1] = __ldg(&eap[(base + j) * 2 + 1]);
            }
            __syncwarp();

            float d0 = 0.f, d1 = 0.f, n0 = 0.f, n1 = 0.f;

            #define CONSUME_SMEM(l, hv)                                          \
            {                                                                    \
                float4 A = my_eap[(l) * 2];                                      \
                float4 B = my_eap[(l) * 2 + 1];                                  \
                float t0 = bc0 + (hv).x, t1 = bc1 + (hv).y;                      \
                t0 = fmaf(A.x, wA[0], t0);  t1 = fmaf(A.x, wB[0], t1);           \
                t0 = fmaf(A.y, wA[1], t0);  t1 = fmaf(A.y, wB[1], t1);           \
                t0 = fmaf(A.z, wA[2], t0);  t1 = fmaf(A.z, wB[2], t1);           \
                t0 = fmaf(A.w, wA[3], t0);  t1 = fmaf(A.w, wB[3], t1);           \
                t0 = fmaf(B.x, wA[4], t0);  t1 = fmaf(B.x, wB[4], t1);           \
                t0 = fmaf(B.y, wA[5], t0);  t1 = fmaf(B.y, wB[5], t1);           \
                t0 = fmaf(B.z, wA[6], t0);  t1 = fmaf(B.z, wB[6], t1);           \
                t0 = fmaf(B.w, wA[7], t0);  t1 = fmaf(B.w, wB[7], t1);           \
                float v0 = fmaxf(t0, 0.f);                                       \
                float v1 = fmaxf(t1, 0.f);                                       \
                float ex0 = __expf(v0);                                          \
                float ex1 = __expf(v1);                                          \
                d0 += ex0;  n0 = fmaf(v0, ex0, n0);                              \
                d1 += ex1;  n1 = fmaf(v1, ex1, n1);                              \
            }

            int l = 0;
            if (staged > 0) {
                float2 h0 = __ldg(&hin[my_src[0] * 32 + lane]);
                float2 h1 = (staged > 1) ? __ldg(&hin[my_src[1] * 32 + lane]) : h0;
                for (; l + 2 < staged; l++) {
                    float2 h2 = __ldg(&hin[my_src[l + 2] * 32 + lane]);
                    CONSUME_SMEM(l, h0);
                    h0 = h1;
                    h1 = h2;
                }
                if (l < staged) { CONSUME_SMEM(l, h0); l++; }
                if (l < staged) { CONSUME_SMEM(l, h1); l++; }
            }
            for (l = staged; l < cnt; l++) {   // overflow tail (P ~ 0)
                int s = __ldg(&g_srcp[base + l]);
                float2 hv = __ldg(&hin[s * 32 + lane]);
                float4 A = __ldg(&eap[(base + l) * 2]);
                float4 B = __ldg(&eap[(base + l) * 2 + 1]);
                float t0 = bc0 + hv.x, t1 = bc1 + hv.y;
                t0 = fmaf(A.x, wA[0], t0);  t1 = fmaf(A.x, wB[0], t1);
                t0 = fmaf(A.y, wA[1], t0);  t1 = fmaf(A.y, wB[1], t1);
                t0 = fmaf(A.z, wA[2], t0);  t1 = fmaf(A.z, wB[2], t1);
                t0 = fmaf(A.w, wA[3], t0);  t1 = fmaf(A.w, wB[3], t1);
                t0 = fmaf(B.x, wA[4], t0);  t1 = fmaf(B.x, wB[4], t1);
                t0 = fmaf(B.y, wA[5], t0);  t1 = fmaf(B.y, wB[5], t1);
                t0 = fmaf(B.z, wA[6], t0);  t1 = fmaf(B.z, wB[6], t1);
                t0 = fmaf(B.w, wA[7], t0);  t1 = fmaf(B.w, wB[7], t1);
                float v0 = fmaxf(t0, 0.f);
                float v1 = fmaxf(t1, 0.f);
                float ex0 = __expf(v0);
                float ex1 = __expf(v1);
                d0 += ex0;  n0 = fmaf(v0, ex0, n0);
                d1 += ex1;  n1 = fmaf(v1, ex1, n1);
            }

            float2 hme = __ldg(&hin[node * 32 + lane]);
            float a0 = hme.x + ((cnt > 0) ? (n0 / d0 + 1e-7f) : 0.f);
            float a1 = hme.y + ((cnt > 0) ? (n1 / d1 + 1e-7f) : 0.f);
            // MLP: y = a @ Wm + bm (64x64 warp shfl-GEMM, paired float2 LDS)
            float acc0 = bm0, acc1 = bm1;
            const float2* wm2 = (const float2*)wms;
            #pragma unroll
            for (int k = 0; k < 32; k++) {
                float2 w = wm2[k * 32 + lane];
                float v = __shfl_sync(0xffffffffu, a0, k);
                acc0 = fmaf(v, w.x, acc0);
                acc1 = fmaf(v, w.y, acc1);
            }
            #pragma unroll
            for (int k = 0; k < 32; k++) {
                float2 w = wm2[(k + 32) * 32 + lane];
                float v = __shfl_sync(0xffffffffu, a1, k);
                acc0 = fmaf(v, w.x, acc0);
                acc1 = fmaf(v, w.y, acc1);
            }
            float* o = g_h + node * 128 + outoff;
            float y0 = o[lane] + acc0, y1 = o[lane + 32] + acc1;
            o[lane] = y0;  o[lane + 32] = y1;
            if (ng) {
                float su = y0 + y1, q = y0 * y0 + y1 * y1;
                #pragma unroll
                for (int d = 16; d > 0; d >>= 1) {
                    su += __shfl_xor_sync(0xffffffffu, su, d);
                    q  += __shfl_xor_sync(0xffffffffu, q, d);
                }
                float mu = su * (1.f / 64.f);
                float rs = rsqrtf(q * (1.f / 64.f) - mu * mu + 1e-5f);
                float r0 = fmaxf((y0 - mu) * rs * __ldg(&ng[lane]) + __ldg(&nb[lane]), 0.f);
                float r1 = fmaxf((y1 - mu) * rs * __ldg(&ng[lane + 32]) + __ldg(&nb[lane + 32]), 0.f);
                hout[node * 32 + lane] = make_float2(r0, r1);
            } else {
                // last phase: reset degree for next replay (owner warp only)
                if (lane == 0) g_cnt[node] = 0;
            }
            __syncwarp();
        }
        if (phase < 3) {
            GRID_BARRIER(phase)
        }
    }
}

// ---------- final: out = relu(LN(h)) @ Wp + bp, ALL 112 cols, one launch -----
__global__ void k_final1(const float* __restrict__ lg, const float* __restrict__ lb,
                         const float* __restrict__ Wp, const float* __restrict__ bp,
                         float* __restrict__ out) {
    extern __shared__ float4 wp4[];     // 128*32 float4 = 64KB dynamic
    int tid = threadIdx.x;
    for (int i = tid; i < 4096; i += blockDim.x) {
        int k = i >> 5, c = i & 31;
        float w0 = Wp[k * 112 + c];
        float w1 = Wp[k * 112 + c + 32];
        float w2 = Wp[k * 112 + c + 64];
        float w3 = (c < 16) ? Wp[k * 112 + c + 96] : 0.f;
        wp4[i] = make_float4(w0, w1, w2, w3);
    }
    __syncthreads();
    int lane = tid & 31;
    int warp = blockIdx.x * (blockDim.x >> 5) + (tid >> 5);
    int nw = gridDim.x * (blockDim.x >> 5);
    bool has3 = lane < 16;
    float bp0 = bp[lane], bp1 = bp[lane + 32], bp2 = bp[lane + 64];
    float bp3 = has3 ? bp[lane + 96] : 0.f;
    float lgv[4], lbv[4];
    #pragma unroll
    for (int i = 0; i < 4; i++) { lgv[i] = lg[lane + i * 32]; lbv[i] = lb[lane + i * 32]; }
    for (int n = warp * 2; n < NN; n += nw * 2) {
        int n2 = n + 1;
        const float* hA = g_h + n * 128;
        const float* hB = g_h + n2 * 128;
        float xA[4], xB[4];
        #pragma unroll
        for (int i = 0; i < 4; i++) { xA[i] = hA[lane + i * 32]; xB[i] = hB[lane + i * 32]; }
        float sA = 0.f, qA = 0.f, sB = 0.f, qB = 0.f;
        #pragma unroll
        for (int i = 0; i < 4; i++) {
            sA += xA[i]; qA += xA[i] * xA[i];
            sB += xB[i]; qB += xB[i] * xB[i];
        }
        #pragma unroll
        for (int d = 16; d > 0; d >>= 1) {
            sA += __shfl_xor_sync(0xffffffffu, sA, d);
            qA += __shfl_xor_sync(0xffffffffu, qA, d);
            sB += __shfl_xor_sync(0xffffffffu, sB, d);
            qB += __shfl_xor_sync(0xffffffffu, qB, d);
        }
        float muA = sA * (1.f / 128.f), muB = sB * (1.f / 128.f);
        float rsA = rsqrtf(qA * (1.f / 128.f) - muA * muA + 1e-5f);
        float rsB = rsqrtf(qB * (1.f / 128.f) - muB * muB + 1e-5f);
        #pragma unroll
        for (int i = 0; i < 4; i++) {
            xA[i] = fmaxf((xA[i] - muA) * rsA * lgv[i] + lbv[i], 0.f);
            xB[i] = fmaxf((xB[i] - muB) * rsB * lgv[i] + lbv[i], 0.f);
        }
        float aA0 = bp0, aA1 = bp1, aA2 = bp2, aA3 = bp3;
        float aB0 = bp0, aB1 = bp1, aB2 = bp2, aB3 = bp3;
        #pragma unroll
        for (int i = 0; i < 4; i++) {
            #pragma unroll
            for (int k = 0; k < 32; k++) {
                float4 w = wp4[(k + i * 32) * 32 + lane];
                float vA = __shfl_sync(0xffffffffu, xA[i], k);
                float vB = __shfl_sync(0xffffffffu, xB[i], k);
                aA0 = fmaf(vA, w.x, aA0);  aA1 = fmaf(vA, w.y, aA1);
                aA2 = fmaf(vA, w.z, aA2);  aA3 = fmaf(vA, w.w, aA3);
                aB0 = fmaf(vB, w.x, aB0);  aB1 = fmaf(vB, w.y, aB1);
                aB2 = fmaf(vB, w.z, aB2);  aB3 = fmaf(vB, w.w, aB3);
            }
        }
        out[n * 112 + lane] = aA0;
        out[n * 112 + lane + 32] = aA1;
        out[n * 112 + lane + 64] = aA2;
        out[n2 * 112 + lane] = aB0;
        out[n2 * 112 + lane + 32] = aB1;
        out[n2 * 112 + lane + 64] = aB2;
        if (has3) {
            out[n * 112 + lane + 96] = aA3;
            out[n2 * 112 + lane + 96] = aB3;
        }
    }
}

// ---------------- launch ----------------------------------------------------
extern "C" void kernel_launch(void* const* d_in, const int* in_sizes, int n_in,
                              void* d_out, int out_size) {
    const float* x     = (const float*)d_in[0];
    const int*   nidx  = (const int*)d_in[1];
    const int*   ei    = (const int*)d_in[2];
    const float* ea    = (const float*)d_in[3];
    const float* nodef = (const float*)d_in[4];
    const float* Woh   = (const float*)d_in[5];
    const float* boh   = (const float*)d_in[6];
    const float* Wne   = (const float*)d_in[7];
    const float* bne   = (const float*)d_in[8];
    const float* Wee   = (const float*)d_in[9];
    const float* bee   = (const float*)d_in[10];
    const float* lng   = (const float*)d_in[11];
    const float* lnb   = (const float*)d_in[12];
    const float* We    = (const float*)d_in[13];
    const float* be    = (const float*)d_in[14];
    const float* Wm    = (const float*)d_in[15];
    const float* bm    = (const float*)d_in[16];
    const float* lastg = (const float*)d_in[17];
    const float* lastb = (const float*)d_in[18];
    const float* Wp    = (const float*)d_in[19];
    const float* bp    = (const float*)d_in[20];
    float* out = (float*)d_out;

    const int* src = ei;
    const int* dst = ei + EE;

    static int nsm = 0;
    if (nsm == 0) {
        int dev = 0;
        cudaGetDevice(&dev);
        cudaDeviceGetAttribute(&nsm, cudaDevAttrMultiProcessorCount, dev);
        cudaFuncSetAttribute(k_final1, cudaFuncAttributeMaxDynamicSharedMemorySize, 65536);
    }

    k_prep_all<<<nsm * 4, 256>>>(src, dst, (const float4*)ea,
                                 x, nidx, nodef, Woh, boh, Wne, bne,
                                 lng, lnb, Wee, bee, We, be);
    k_gen<<<nsm * 4, 256>>>(Wm, bm, lng, lnb);
    k_final1<<<nsm * 3, 256, 65536>>>(lastg, lastb, Wp, bp, out);
}

// round 16
// speedup vs baseline: 1.0465x; 1.0465x over previous
#include <cuda_runtime.h>

#define NN 100000
#define EE 1600000
#define BUCKET 96        // fixed slots per node (Poisson(16): P(deg>96) ~ e^-40)
#define SCAP 64          // per-warp smem-staged edge cap (P(deg>64) ~ 2e-13)

// ---------------- scratch (static device globals; no allocation) ------------
__device__ float  g_h[NN * 128];          // node features, updated in place
__device__ float2 g_hblkA[NN * 32];       // ping-pong relu(LN(half)) buffers
__device__ float2 g_hblkB[NN * 32];
__device__ int    g_cnt[NN];              // degree; zero-init; re-zeroed by k_gen ph3
__device__ int    g_srcp[NN * BUCKET];    // src bucketed by dst
__device__ float  g_eap[NN * BUCKET * 8]; // edge_attr bucketed by dst (307MB)
__device__ float  g_wc[4 * 8 * 64];       // folded W_ee @ We per block
__device__ float  g_bc[4 * 64];           // folded bias per block
__device__ int    g_gen;                  // grid-barrier generation (monotonic)
__device__ int    g_count;                // grid-barrier counter (resets to 0)

#define GRID_BARRIER(k)                                                       \
    __syncthreads();                                                          \
    if (tid == 0) {                                                           \
        __threadfence();                                                      \
        int t_ = atomicAdd(&g_count, 1);                                      \
        if (t_ == nblk - 1) {                                                 \
            atomicExch(&g_count, 0);                                          \
            __threadfence();                                                  \
            atomicAdd(&g_gen, 1);                                             \
        } else {                                                              \
            while (*(volatile int*)&g_gen < s_gen_entry + (k) + 1)            \
                __nanosleep(64);                                              \
        }                                                                     \
        __threadfence();                                                      \
    }                                                                         \
    __syncthreads();

// ===== prep: wc | encode(+LN0) | direct bucket scatter — single phase ========
// NO min-blocks bound: high-reg compile gives deep per-thread ILP in the
// scatter chain (R14: 170us at occ 12%); the 64-reg cap was SLOWER (R15).
__global__ void __launch_bounds__(256) k_prep_all(
        const int* __restrict__ src, const int* __restrict__ dst,
        const float4* __restrict__ ea,
        const float* __restrict__ x, const int* __restrict__ nidx,
        const float* __restrict__ nodef,
        const float* __restrict__ Woh, const float* __restrict__ boh,
        const float* __restrict__ Wne, const float* __restrict__ bne,
        const float* __restrict__ ln0g, const float* __restrict__ ln0b,
        const float* __restrict__ Wee, const float* __restrict__ bee,
        const float* __restrict__ We, const float* __restrict__ be) {
    __shared__ float s_woh[64], s_boh[8], s_wne[2048], s_bne[128];
    int tid = threadIdx.x, lane = tid & 31, wid = tid >> 5;
    int nblk = gridDim.x, b = blockIdx.x;
    int gw = b * 8 + wid;

    // ---- wc: warp per output (2304 outputs), tiny ----
    for (int idx = gw; idx < 2304; idx += nblk * 8) {
        if (idx < 2048) {
            int bb = idx >> 9, k = (idx >> 6) & 7, c = idx & 63;
            float s = 0.f;
            for (int j = lane; j < 128; j += 32)
                s += Wee[k * 128 + j] * We[(bb * 128 + j) * 64 + c];
            #pragma unroll
            for (int d = 16; d > 0; d >>= 1) s += __shfl_xor_sync(0xffffffffu, s, d);
            if (lane == 0) g_wc[idx] = s;
        } else {
            int i2 = idx - 2048;
            int bb = i2 >> 6, c = i2 & 63;
            float s = 0.f;
            for (int j = lane; j < 128; j += 32)
                s += bee[j] * We[(bb * 128 + j) * 64 + c];
            #pragma unroll
            for (int d = 16; d > 0; d >>= 1) s += __shfl_xor_sync(0xffffffffu, s, d);
            if (lane == 0) g_bc[i2] = be[i2] + s;
        }
    }
    // stage encoder weights
    for (int i = tid; i < 64; i += 256) s_woh[i] = Woh[i];
    for (int i = tid; i < 8; i += 256) s_boh[i] = boh[i];
    for (int i = tid; i < 2048; i += 256) s_wne[i] = Wne[i];
    for (int i = tid; i < 128; i += 256) s_bne[i] = bne[i];
    __syncthreads();

    for (int half = 0; half < 2; half++) {
        // even blocks: scatter then encode; odd blocks: encode then scatter
        if ((half ^ (b & 1)) == 0) {
            // ---- scatter into fixed-stride buckets ----
            float4* o = (float4*)g_eap;
            for (int i = b * 256 + tid; i < EE; i += nblk * 256) {
                int d = dst[i];
                int pos = atomicAdd(&g_cnt[d], 1);
                int p = d * BUCKET + pos;
                g_srcp[p] = src[i];
                o[p * 2]     = __ldg(&ea[i * 2]);
                o[p * 2 + 1] = __ldg(&ea[i * 2 + 1]);
            }
        } else {
            // ---- encode + fused LN/relu block 0 -> hblkA ----
            for (int n = gw; n < NN; n += nblk * 8) {
                int s = nidx[n];
                float4 a  = *(const float4*)(nodef + s * 8);
                float4 b4 = *(const float4*)(nodef + s * 8 + 4);
                float nf1[8] = {a.x, a.y, a.z, a.w, b4.x, b4.y, b4.z, b4.w};
                float4 xa = *(const float4*)(x + n * 8);
                float4 xb = *(const float4*)(x + n * 8 + 4);
                float xv[8] = {xa.x, xa.y, xa.z, xa.w, xb.x, xb.y, xb.z, xb.w};
                float nf2[8];
                #pragma unroll
                for (int j = 0; j < 8; j++) {
                    float t = s_boh[j];
                    #pragma unroll
                    for (int i = 0; i < 8; i++) t += xv[i] * s_woh[i * 8 + j];
                    nf2[j] = t;
                }
                float acc[4];
                #pragma unroll
                for (int cc = 0; cc < 4; cc++) {
                    int c = lane + cc * 32;
                    float t = s_bne[c];
                    #pragma unroll
                    for (int k = 0; k < 8; k++) t += nf1[k] * s_wne[k * 128 + c];
                    #pragma unroll
                    for (int k = 0; k < 8; k++) t += nf2[k] * s_wne[(8 + k) * 128 + c];
                    g_h[n * 128 + c] = t;
                    acc[cc] = t;
                }
                float v0 = acc[2], v1 = acc[3];
                float su = v0 + v1, q = v0 * v0 + v1 * v1;
                #pragma unroll
                for (int d = 16; d > 0; d >>= 1) {
                    su += __shfl_xor_sync(0xffffffffu, su, d);
                    q  += __shfl_xor_sync(0xffffffffu, q, d);
                }
                float mu = su * (1.f / 64.f);
                float rs = rsqrtf(q * (1.f / 64.f) - mu * mu + 1e-5f);
                float r0 = fmaxf((v0 - mu) * rs * ln0g[lane] + ln0b[lane], 0.f);
                float r1 = fmaxf((v1 - mu) * rs * ln0g[lane + 32] + ln0b[lane + 32], 0.f);
                g_hblkA[n * 32 + lane] = make_float2(r0, r1);
            }
        }
    }
}

// ----- persistent 4-phase GEN: warp-independent, per-warp smem staging ------
// Each warp owns a node stream; stages its node's edges (<=SCAP) into its own
// smem slice (__syncwarp only). Depth-3 pipeline on the hblk gather.
// MLP weights quad-packed: one LDS.128 covers 2 k-rows x 2 channels.
// Unshifted softmax (exact: msg bounded; weights invariant to shift/+eps;
// agg = sum(relu*w) + eps, guarded so empty nodes stay exactly 0).
// Phase 3 zeroes g_cnt[node] after its last read (replay-invariant state).
__global__ void __launch_bounds__(256, 4) k_gen(
        const float* __restrict__ Wm, const float* __restrict__ bm,
        const float* __restrict__ lng, const float* __restrict__ lnb) {
    __shared__ float4 wms4[1024];           // quad: (W[2q][c],W[2q][c+32],W[2q+1][c],W[2q+1][c+32])
    __shared__ float4 s_eap[8 * SCAP * 2];  // 16KB, per-warp slices
    __shared__ int s_src[8 * SCAP];         // 2KB
    __shared__ int s_gen_entry;
    int tid = threadIdx.x;
    int lane = tid & 31, wid = tid >> 5;
    if (tid == 0) s_gen_entry = *(volatile int*)&g_gen;
    int nblk = gridDim.x;
    int gwarp = blockIdx.x * 8 + wid;
    int nwarp = nblk * 8;
    const float4* eap = (const float4*)g_eap;
    float4* my_eap = s_eap + wid * SCAP * 2;
    int* my_src = s_src + wid * SCAP;

    for (int phase = 0; phase < 4; phase++) {
        __syncthreads();
        {
            const float* W = Wm + phase * 4096;
            for (int i = tid; i < 1024; i += 256) {
                int q = i >> 5, c = i & 31;
                wms4[i] = make_float4(W[(2 * q) * 64 + c], W[(2 * q) * 64 + c + 32],
                                      W[(2 * q + 1) * 64 + c], W[(2 * q + 1) * 64 + c + 32]);
            }
        }
        __syncthreads();
        const float2* __restrict__ hin = (phase & 1) ? g_hblkB : g_hblkA;
        float2* __restrict__ hout = (phase & 1) ? g_hblkA : g_hblkB;
        int outoff = (phase & 1) ? 64 : 0;
        const float* ng = (phase < 3) ? (lng + (phase + 1) * 64) : (const float*)0;
        const float* nb = (phase < 3) ? (lnb + (phase + 1) * 64) : (const float*)0;
        const float* Wc = g_wc + phase * 512;
        float wA[8], wB[8];
        #pragma unroll
        for (int k = 0; k < 8; k++) {
            wA[k] = __ldg(&Wc[k * 64 + lane]);
            wB[k] = __ldg(&Wc[k * 64 + lane + 32]);
        }
        float bc0 = __ldg(&g_bc[phase * 64 + lane]);
        float bc1 = __ldg(&g_bc[phase * 64 + lane + 32]);
        float bm0 = __ldg(&bm[phase * 64 + lane]);
        float bm1 = __ldg(&bm[phase * 64 + lane + 32]);

        for (int node = gwarp; node < NN; node += nwarp) {
            int cnt = *(volatile int*)&g_cnt[node];
            int base = node * BUCKET;
            int staged = min(cnt, SCAP);
            // per-warp staging, warp-local sync only
            for (int j = lane; j < staged; j += 32) {
                my_src[j] = __ldg(&g_srcp[base + j]);
                my_eap[j * 2]     = __ldg(&eap[(base + j) * 2]);
                my_eap[j * 2 + 1] = __ldg(&eap[(base + j) * 2 + 1]);
            }
            __syncwarp();

            float d0 = 0.f, d1 = 0.f, n0 = 0.f, n1 = 0.f;

            #define CONSUME_SMEM(l, hv)                                          \
            {                                                                    \
                float4 A = my_eap[(l) * 2];                                      \
                float4 B = my_eap[(l) * 2 + 1];                                  \
                float t0 = bc0 + (hv).x, t1 = bc1 + (hv).y;                      \
                t0 = fmaf(A.x, wA[0], t0);  t1 = fmaf(A.x, wB[0], t1);           \
                t0 = fmaf(A.y, wA[1], t0);  t1 = fmaf(A.y, wB[1], t1);           \
                t0 = fmaf(A.z, wA[2], t0);  t1 = fmaf(A.z, wB[2], t1);           \
                t0 = fmaf(A.w, wA[3], t0);  t1 = fmaf(A.w, wB[3], t1);           \
                t0 = fmaf(B.x, wA[4], t0);  t1 = fmaf(B.x, wB[4], t1);           \
                t0 = fmaf(B.y, wA[5], t0);  t1 = fmaf(B.y, wB[5], t1);           \
                t0 = fmaf(B.z, wA[6], t0);  t1 = fmaf(B.z, wB[6], t1);           \
                t0 = fmaf(B.w, wA[7], t0);  t1 = fmaf(B.w, wB[7], t1);           \
                float v0 = fmaxf(t0, 0.f);                                       \
                float v1 = fmaxf(t1, 0.f);                                       \
                float ex0 = __expf(v0);                                          \
                float ex1 = __expf(v1);                                          \
                d0 += ex0;  n0 = fmaf(v0, ex0, n0);                              \
                d1 += ex1;  n1 = fmaf(v1, ex1, n1);                              \
            }

            int l = 0;
            if (staged > 0) {
                float2 h0 = __ldg(&hin[my_src[0] * 32 + lane]);
                float2 h1 = (staged > 1) ? __ldg(&hin[my_src[1] * 32 + lane]) : h0;
                for (; l + 2 < staged; l++) {
                    float2 h2 = __ldg(&hin[my_src[l + 2] * 32 + lane]);
                    CONSUME_SMEM(l, h0);
                    h0 = h1;
                    h1 = h2;
                }
                if (l < staged) { CONSUME_SMEM(l, h0); l++; }
                if (l < staged) { CONSUME_SMEM(l, h1); l++; }
            }
            for (l = staged; l < cnt; l++) {   // overflow tail (P ~ 0)
                int s = __ldg(&g_srcp[base + l]);
                float2 hv = __ldg(&hin[s * 32 + lane]);
                float4 A = __ldg(&eap[(base + l) * 2]);
                float4 B = __ldg(&eap[(base + l) * 2 + 1]);
                float t0 = bc0 + hv.x, t1 = bc1 + hv.y;
                t0 = fmaf(A.x, wA[0], t0);  t1 = fmaf(A.x, wB[0], t1);
                t0 = fmaf(A.y, wA[1], t0);  t1 = fmaf(A.y, wB[1], t1);
                t0 = fmaf(A.z, wA[2], t0);  t1 = fmaf(A.z, wB[2], t1);
                t0 = fmaf(A.w, wA[3], t0);  t1 = fmaf(A.w, wB[3], t1);
                t0 = fmaf(B.x, wA[4], t0);  t1 = fmaf(B.x, wB[4], t1);
                t0 = fmaf(B.y, wA[5], t0);  t1 = fmaf(B.y, wB[5], t1);
                t0 = fmaf(B.z, wA[6], t0);  t1 = fmaf(B.z, wB[6], t1);
                t0 = fmaf(B.w, wA[7], t0);  t1 = fmaf(B.w, wB[7], t1);
                float v0 = fmaxf(t0, 0.f);
                float v1 = fmaxf(t1, 0.f);
                float ex0 = __expf(v0);
                float ex1 = __expf(v1);
                d0 += ex0;  n0 = fmaf(v0, ex0, n0);
                d1 += ex1;  n1 = fmaf(v1, ex1, n1);
            }

            float2 hme = __ldg(&hin[node * 32 + lane]);
            float a0 = hme.x + ((cnt > 0) ? (n0 / d0 + 1e-7f) : 0.f);
            float a1 = hme.y + ((cnt > 0) ? (n1 / d1 + 1e-7f) : 0.f);
            // MLP: y = a @ Wm + bm (64x64 warp shfl-GEMM, quad float4 LDS)
            float acc0 = bm0, acc1 = bm1;
            #pragma unroll
            for (int q = 0; q < 16; q++) {
                float4 w = wms4[q * 32 + lane];
                float v0 = __shfl_sync(0xffffffffu, a0, 2 * q);
                float v1 = __shfl_sync(0xffffffffu, a0, 2 * q + 1);
                acc0 = fmaf(v0, w.x, acc0);  acc1 = fmaf(v0, w.y, acc1);
                acc0 = fmaf(v1, w.z, acc0);  acc1 = fmaf(v1, w.w, acc1);
            }
            #pragma unroll
            for (int q = 0; q < 16; q++) {
                float4 w = wms4[(q + 16) * 32 + lane];
                float v0 = __shfl_sync(0xffffffffu, a1, 2 * q);
                float v1 = __shfl_sync(0xffffffffu, a1, 2 * q + 1);
                acc0 = fmaf(v0, w.x, acc0);  acc1 = fmaf(v0, w.y, acc1);
                acc0 = fmaf(v1, w.z, acc0);  acc1 = fmaf(v1, w.w, acc1);
            }
            float* o = g_h + node * 128 + outoff;
            float y0 = o[lane] + acc0, y1 = o[lane + 32] + acc1;
            o[lane] = y0;  o[lane + 32] = y1;
            if (ng) {
                float su = y0 + y1, q = y0 * y0 + y1 * y1;
                #pragma unroll
                for (int d = 16; d > 0; d >>= 1) {
                    su += __shfl_xor_sync(0xffffffffu, su, d);
                    q  += __shfl_xor_sync(0xffffffffu, q, d);
                }
                float mu = su * (1.f / 64.f);
                float rs = rsqrtf(q * (1.f / 64.f) - mu * mu + 1e-5f);
                float r0 = fmaxf((y0 - mu) * rs * __ldg(&ng[lane]) + __ldg(&nb[lane]), 0.f);
                float r1 = fmaxf((y1 - mu) * rs * __ldg(&ng[lane + 32]) + __ldg(&nb[lane + 32]), 0.f);
                hout[node * 32 + lane] = make_float2(r0, r1);
            } else {
                // last phase: reset degree for next replay (owner warp only)
                if (lane == 0) g_cnt[node] = 0;
            }
            __syncwarp();
        }
        if (phase < 3) {
            GRID_BARRIER(phase)
        }
    }
}

// ---------- final: out = relu(LN(h)) @ Wp + bp, ALL 112 cols, one launch -----
__global__ void k_final1(const float* __restrict__ lg, const float* __restrict__ lb,
                         const float* __restrict__ Wp, const float* __restrict__ bp,
                         float* __restrict__ out) {
    extern __shared__ float4 wp4[];     // 128*32 float4 = 64KB dynamic
    int tid = threadIdx.x;
    for (int i = tid; i < 4096; i += blockDim.x) {
        int k = i >> 5, c = i & 31;
        float w0 = Wp[k * 112 + c];
        float w1 = Wp[k * 112 + c + 32];
        float w2 = Wp[k * 112 + c + 64];
        float w3 = (c < 16) ? Wp[k * 112 + c + 96] : 0.f;
        wp4[i] = make_float4(w0, w1, w2, w3);
    }
    __syncthreads();
    int lane = tid & 31;
    int warp = blockIdx.x * (blockDim.x >> 5) + (tid >> 5);
    int nw = gridDim.x * (blockDim.x >> 5);
    bool has3 = lane < 16;
    float bp0 = bp[lane], bp1 = bp[lane + 32], bp2 = bp[lane + 64];
    float bp3 = has3 ? bp[lane + 96] : 0.f;
    float lgv[4], lbv[4];
    #pragma unroll
    for (int i = 0; i < 4; i++) { lgv[i] = lg[lane + i * 32]; lbv[i] = lb[lane + i * 32]; }
    for (int n = warp * 2; n < NN; n += nw * 2) {
        int n2 = n + 1;
        const float* hA = g_h + n * 128;
        const float* hB = g_h + n2 * 128;
        float xA[4], xB[4];
        #pragma unroll
        for (int i = 0; i < 4; i++) { xA[i] = hA[lane + i * 32]; xB[i] = hB[lane + i * 32]; }
        float sA = 0.f, qA = 0.f, sB = 0.f, qB = 0.f;
        #pragma unroll
        for (int i = 0; i < 4; i++) {
            sA += xA[i]; qA += xA[i] * xA[i];
            sB += xB[i]; qB += xB[i] * xB[i];
        }
        #pragma unroll
        for (int d = 16; d > 0; d >>= 1) {
            sA += __shfl_xor_sync(0xffffffffu, sA, d);
            qA += __shfl_xor_sync(0xffffffffu, qA, d);
            sB += __shfl_xor_sync(0xffffffffu, sB, d);
            qB += __shfl_xor_sync(0xffffffffu, qB, d);
        }
        float muA = sA * (1.f / 128.f), muB = sB * (1.f / 128.f);
        float rsA = rsqrtf(qA * (1.f / 128.f) - muA * muA + 1e-5f);
        float rsB = rsqrtf(qB * (1.f / 128.f) - muB * muB + 1e-5f);
        #pragma unroll
        for (int i = 0; i < 4; i++) {
            xA[i] = fmaxf((xA[i] - muA) * rsA * lgv[i] + lbv[i], 0.f);
            xB[i] = fmaxf((xB[i] - muB) * rsB * lgv[i] + lbv[i], 0.f);
        }
        float aA0 = bp0, aA1 = bp1, aA2 = bp2, aA3 = bp3;
        float aB0 = bp0, aB1 = bp1, aB2 = bp2, aB3 = bp3;
        #pragma unroll
        for (int i = 0; i < 4; i++) {
            #pragma unroll
            for (int k = 0; k < 32; k++) {
                float4 w = wp4[(k + i * 32) * 32 + lane];
                float vA = __shfl_sync(0xffffffffu, xA[i], k);
                float vB = __shfl_sync(0xffffffffu, xB[i], k);
                aA0 = fmaf(vA, w.x, aA0);  aA1 = fmaf(vA, w.y, aA1);
                aA2 = fmaf(vA, w.z, aA2);  aA3 = fmaf(vA, w.w, aA3);
                aB0 = fmaf(vB, w.x, aB0);  aB1 = fmaf(vB, w.y, aB1);
                aB2 = fmaf(vB, w.z, aB2);  aB3 = fmaf(vB, w.w, aB3);
            }
        }
        out[n * 112 + lane] = aA0;
        out[n * 112 + lane + 32] = aA1;
        out[n * 112 + lane + 64] = aA2;
        out[n2 * 112 + lane] = aB0;
        out[n2 * 112 + lane + 32] = aB1;
        out[n2 * 112 + lane + 64] = aB2;
        if (has3) {
            out[n * 112 + lane + 96] = aA3;
            out[n2 * 112 + lane + 96] = aB3;
        }
    }
}

// ---------------- launch ----------------------------------------------------
extern "C" void kernel_launch(void* const* d_in, const int* in_sizes, int n_in,
                              void* d_out, int out_size) {
    const float* x     = (const float*)d_in[0];
    const int*   nidx  = (const int*)d_in[1];
    const int*   ei    = (const int*)d_in[2];
    const float* ea    = (const float*)d_in[3];
    const float* nodef = (const float*)d_in[4];
    const float* Woh   = (const float*)d_in[5];
    const float* boh   = (const float*)d_in[6];
    const float* Wne   = (const float*)d_in[7];
    const float* bne   = (const float*)d_in[8];
    const float* Wee   = (const float*)d_in[9];
    const float* bee   = (const float*)d_in[10];
    const float* lng   = (const float*)d_in[11];
    const float* lnb   = (const float*)d_in[12];
    const float* We    = (const float*)d_in[13];
    const float* be    = (const float*)d_in[14];
    const float* Wm    = (const float*)d_in[15];
    const float* bm    = (const float*)d_in[16];
    const float* lastg = (const float*)d_in[17];
    const float* lastb = (const float*)d_in[18];
    const float* Wp    = (const float*)d_in[19];
    const float* bp    = (const float*)d_in[20];
    float* out = (float*)d_out;

    const int* src = ei;
    const int* dst = ei + EE;

    static int nsm = 0;
    if (nsm == 0) {
        int dev = 0;
        cudaGetDevice(&dev);
        cudaDeviceGetAttribute(&nsm, cudaDevAttrMultiProcessorCount, dev);
        cudaFuncSetAttribute(k_final1, cudaFuncAttributeMaxDynamicSharedMemorySize, 65536);
    }

    k_prep_all<<<nsm * 4, 256>>>(src, dst, (const float4*)ea,
                                 x, nidx, nodef, Woh, boh, Wne, bne,
                                 lng, lnb, Wee, bee, We, be);
    k_gen<<<nsm * 4, 256>>>(Wm, bm, lng, lnb);
    k_final1<<<nsm * 3, 256, 65536>>>(lastg, lastb, Wp, bp, out);
}

// round 17
// speedup vs baseline: 1.0898x; 1.0413x over previous
#include <cuda_runtime.h>

#define NN 100000
#define EE 1600000
#define BUCKET 96        // fixed slots per node (Poisson(16): P(deg>96) ~ e^-40)
#define SCAP 64          // per-warp smem-staged edge cap (P(deg>64) ~ 2e-13)

// ---------------- scratch (static device globals; no allocation) ------------
__device__ float  g_h[NN * 128];          // node features, updated in place
__device__ float2 g_hblkA[NN * 32];       // ping-pong relu(LN(half)) buffers
__device__ float2 g_hblkB[NN * 32];
__device__ int    g_cnt[NN];              // degree; zero-init; re-zeroed by k_gen ph3
__device__ int    g_srcp[NN * BUCKET];    // src bucketed by dst
__device__ float  g_eap[NN * BUCKET * 8]; // edge_attr bucketed by dst (307MB)
__device__ float  g_wc[4 * 8 * 64];       // folded W_ee @ We per block
__device__ float  g_bc[4 * 64];           // folded bias per block
__device__ int    g_gen;                  // grid-barrier generation (monotonic)
__device__ int    g_count;                // grid-barrier counter (resets to 0)

#define GRID_BARRIER(k)                                                       \
    __syncthreads();                                                          \
    if (tid == 0) {                                                           \
        __threadfence();                                                      \
        int t_ = atomicAdd(&g_count, 1);                                      \
        if (t_ == nblk - 1) {                                                 \
            atomicExch(&g_count, 0);                                          \
            __threadfence();                                                  \
            atomicAdd(&g_gen, 1);                                             \
        } else {                                                              \
            while (*(volatile int*)&g_gen < s_gen_entry + (k) + 1)            \
                __nanosleep(64);                                              \
        }                                                                     \
        __threadfence();                                                      \
    }                                                                         \
    __syncthreads();

// ===== prep: wc | encode(+LN0) | direct bucket scatter — single phase ========
// launch_bounds(256,2): ~128-reg cap -> 2 blocks/SM. Middle ground between
// R14 (179 regs / 1 blk / 166us, warp-starved) and R15 (64 regs / 4 blk /
// 223us, ILP-starved).
__global__ void __launch_bounds__(256, 2) k_prep_all(
        const int* __restrict__ src, const int* __restrict__ dst,
        const float4* __restrict__ ea,
        const float* __restrict__ x, const int* __restrict__ nidx,
        const float* __restrict__ nodef,
        const float* __restrict__ Woh, const float* __restrict__ boh,
        const float* __restrict__ Wne, const float* __restrict__ bne,
        const float* __restrict__ ln0g, const float* __restrict__ ln0b,
        const float* __restrict__ Wee, const float* __restrict__ bee,
        const float* __restrict__ We, const float* __restrict__ be) {
    __shared__ float s_woh[64], s_boh[8], s_wne[2048], s_bne[128];
    int tid = threadIdx.x, lane = tid & 31, wid = tid >> 5;
    int nblk = gridDim.x, b = blockIdx.x;
    int gw = b * 8 + wid;

    // ---- wc: warp per output (2304 outputs), tiny ----
    for (int idx = gw; idx < 2304; idx += nblk * 8) {
        if (idx < 2048) {
            int bb = idx >> 9, k = (idx >> 6) & 7, c = idx & 63;
            float s = 0.f;
            for (int j = lane; j < 128; j += 32)
                s += Wee[k * 128 + j] * We[(bb * 128 + j) * 64 + c];
            #pragma unroll
            for (int d = 16; d > 0; d >>= 1) s += __shfl_xor_sync(0xffffffffu, s, d);
            if (lane == 0) g_wc[idx] = s;
        } else {
            int i2 = idx - 2048;
            int bb = i2 >> 6, c = i2 & 63;
            float s = 0.f;
            for (int j = lane; j < 128; j += 32)
                s += bee[j] * We[(bb * 128 + j) * 64 + c];
            #pragma unroll
            for (int d = 16; d > 0; d >>= 1) s += __shfl_xor_sync(0xffffffffu, s, d);
            if (lane == 0) g_bc[i2] = be[i2] + s;
        }
    }
    // stage encoder weights
    for (int i = tid; i < 64; i += 256) s_woh[i] = Woh[i];
    for (int i = tid; i < 8; i += 256) s_boh[i] = boh[i];
    for (int i = tid; i < 2048; i += 256) s_wne[i] = Wne[i];
    for (int i = tid; i < 128; i += 256) s_bne[i] = bne[i];
    __syncthreads();

    for (int half = 0; half < 2; half++) {
        // even blocks: scatter then encode; odd blocks: encode then scatter
        if ((half ^ (b & 1)) == 0) {
            // ---- scatter into fixed-stride buckets ----
            float4* o = (float4*)g_eap;
            for (int i = b * 256 + tid; i < EE; i += nblk * 256) {
                int d = dst[i];
                int pos = atomicAdd(&g_cnt[d], 1);
                int p = d * BUCKET + pos;
                g_srcp[p] = src[i];
                o[p * 2]     = __ldg(&ea[i * 2]);
                o[p * 2 + 1] = __ldg(&ea[i * 2 + 1]);
            }
        } else {
            // ---- encode + fused LN/relu block 0 -> hblkA ----
            for (int n = gw; n < NN; n += nblk * 8) {
                int s = nidx[n];
                float4 a  = *(const float4*)(nodef + s * 8);
                float4 b4 = *(const float4*)(nodef + s * 8 + 4);
                float nf1[8] = {a.x, a.y, a.z, a.w, b4.x, b4.y, b4.z, b4.w};
                float4 xa = *(const float4*)(x + n * 8);
                float4 xb = *(const float4*)(x + n * 8 + 4);
                float xv[8] = {xa.x, xa.y, xa.z, xa.w, xb.x, xb.y, xb.z, xb.w};
                float nf2[8];
                #pragma unroll
                for (int j = 0; j < 8; j++) {
                    float t = s_boh[j];
                    #pragma unroll
                    for (int i = 0; i < 8; i++) t += xv[i] * s_woh[i * 8 + j];
                    nf2[j] = t;
                }
                float acc[4];
                #pragma unroll
                for (int cc = 0; cc < 4; cc++) {
                    int c = lane + cc * 32;
                    float t = s_bne[c];
                    #pragma unroll
                    for (int k = 0; k < 8; k++) t += nf1[k] * s_wne[k * 128 + c];
                    #pragma unroll
                    for (int k = 0; k < 8; k++) t += nf2[k] * s_wne[(8 + k) * 128 + c];
                    g_h[n * 128 + c] = t;
                    acc[cc] = t;
                }
                float v0 = acc[2], v1 = acc[3];
                float su = v0 + v1, q = v0 * v0 + v1 * v1;
                #pragma unroll
                for (int d = 16; d > 0; d >>= 1) {
                    su += __shfl_xor_sync(0xffffffffu, su, d);
                    q  += __shfl_xor_sync(0xffffffffu, q, d);
                }
                float mu = su * (1.f / 64.f);
                float rs = rsqrtf(q * (1.f / 64.f) - mu * mu + 1e-5f);
                float r0 = fmaxf((v0 - mu) * rs * ln0g[lane] + ln0b[lane], 0.f);
                float r1 = fmaxf((v1 - mu) * rs * ln0g[lane + 32] + ln0b[lane + 32], 0.f);
                g_hblkA[n * 32 + lane] = make_float2(r0, r1);
            }
        }
    }
}

// ----- persistent 4-phase GEN: warp-independent, per-warp smem staging ------
// Each warp owns a node stream; stages its node's edges (<=SCAP) into its own
// smem slice (__syncwarp only). Depth-3 pipeline on the hblk gather.
// MLP: paired float2 weights (R14-proven). LN params hoisted out of node loop.
// Unshifted softmax (exact: msg bounded; weights invariant to shift/+eps;
// agg = sum(relu*w) + eps, guarded so empty nodes stay exactly 0).
// Phase 3 zeroes g_cnt[node] after its last read (replay-invariant state).
__global__ void __launch_bounds__(256, 4) k_gen(
        const float* __restrict__ Wm, const float* __restrict__ bm,
        const float* __restrict__ lng, const float* __restrict__ lnb) {
    __shared__ float wms[4096];             // paired: (w[k][c], w[k][c+32])
    __shared__ float4 s_eap[8 * SCAP * 2];  // 16KB, per-warp slices
    __shared__ int s_src[8 * SCAP];         // 2KB
    __shared__ int s_gen_entry;
    int tid = threadIdx.x;
    int lane = tid & 31, wid = tid >> 5;
    if (tid == 0) s_gen_entry = *(volatile int*)&g_gen;
    int nblk = gridDim.x;
    int gwarp = blockIdx.x * 8 + wid;
    int nwarp = nblk * 8;
    const float4* eap = (const float4*)g_eap;
    float4* my_eap = s_eap + wid * SCAP * 2;
    int* my_src = s_src + wid * SCAP;

    for (int phase = 0; phase < 4; phase++) {
        __syncthreads();
        for (int i = tid; i < 4096; i += 256) {
            int k = i >> 6, c = i & 63;
            int col = (c >> 1) + ((c & 1) << 5);
            wms[i] = Wm[phase * 4096 + k * 64 + col];
        }
        __syncthreads();
        const float2* __restrict__ hin = (phase & 1) ? g_hblkB : g_hblkA;
        float2* __restrict__ hout = (phase & 1) ? g_hblkA : g_hblkB;
        int outoff = (phase & 1) ? 64 : 0;
        bool hasnext = (phase < 3);
        // hoisted loop-invariant LN params for the next block
        float g0 = 0.f, g1 = 0.f, nb0 = 0.f, nb1 = 0.f;
        if (hasnext) {
            const float* ng = lng + (phase + 1) * 64;
            const float* nb = lnb + (phase + 1) * 64;
            g0 = __ldg(&ng[lane]);  g1 = __ldg(&ng[lane + 32]);
            nb0 = __ldg(&nb[lane]); nb1 = __ldg(&nb[lane + 32]);
        }
        const float* Wc = g_wc + phase * 512;
        float wA[8], wB[8];
        #pragma unroll
        for (int k = 0; k < 8; k++) {
            wA[k] = __ldg(&Wc[k * 64 + lane]);
            wB[k] = __ldg(&Wc[k * 64 + lane + 32]);
        }
        float bc0 = __ldg(&g_bc[phase * 64 + lane]);
        float bc1 = __ldg(&g_bc[phase * 64 + lane + 32]);
        float bm0 = __ldg(&bm[phase * 64 + lane]);
        float bm1 = __ldg(&bm[phase * 64 + lane + 32]);

        for (int node = gwarp; node < NN; node += nwarp) {
            int cnt = *(volatile int*)&g_cnt[node];
            int base = node * BUCKET;
            int staged = min(cnt, SCAP);
            // per-warp staging, warp-local sync only
            for (int j = lane; j < staged; j += 32) {
                my_src[j] = __ldg(&g_srcp[base + j]);
                my_eap[j * 2]     = __ldg(&eap[(base + j) * 2]);
                my_eap[j * 2 + 1] = __ldg(&eap[(base + j) * 2 + 1]);
            }
            __syncwarp();

            float d0 = 0.f, d1 = 0.f, n0 = 0.f, n1 = 0.f;

            #define CONSUME_SMEM(l, hv)                                          \
            {                                                                    \
                float4 A = my_eap[(l) * 2];                                      \
                float4 B = my_eap[(l) * 2 + 1];                                  \
                float t0 = bc0 + (hv).x, t1 = bc1 + (hv).y;                      \
                t0 = fmaf(A.x, wA[0], t0);  t1 = fmaf(A.x, wB[0], t1);           \
                t0 = fmaf(A.y, wA[1], t0);  t1 = fmaf(A.y, wB[1], t1);           \
                t0 = fmaf(A.z, wA[2], t0);  t1 = fmaf(A.z, wB[2], t1);           \
                t0 = fmaf(A.w, wA[3], t0);  t1 = fmaf(A.w, wB[3], t1);           \
                t0 = fmaf(B.x, wA[4], t0);  t1 = fmaf(B.x, wB[4], t1);           \
                t0 = fmaf(B.y, wA[5], t0);  t1 = fmaf(B.y, wB[5], t1);           \
                t0 = fmaf(B.z, wA[6], t0);  t1 = fmaf(B.z, wB[6], t1);           \
                t0 = fmaf(B.w, wA[7], t0);  t1 = fmaf(B.w, wB[7], t1);           \
                float v0 = fmaxf(t0, 0.f);                                       \
                float v1 = fmaxf(t1, 0.f);                                       \
                float ex0 = __expf(v0);                                          \
                float ex1 = __expf(v1);                                          \
                d0 += ex0;  n0 = fmaf(v0, ex0, n0);                              \
                d1 += ex1;  n1 = fmaf(v1, ex1, n1);                              \
            }

            int l = 0;
            if (staged > 0) {
                float2 h0 = __ldg(&hin[my_src[0] * 32 + lane]);
                float2 h1 = (staged > 1) ? __ldg(&hin[my_src[1] * 32 + lane]) : h0;
                for (; l + 2 < staged; l++) {
                    float2 h2 = __ldg(&hin[my_src[l + 2] * 32 + lane]);
                    CONSUME_SMEM(l, h0);
                    h0 = h1;
                    h1 = h2;
                }
                if (l < staged) { CONSUME_SMEM(l, h0); l++; }
                if (l < staged) { CONSUME_SMEM(l, h1); l++; }
            }
            for (l = staged; l < cnt; l++) {   // overflow tail (P ~ 0)
                int s = __ldg(&g_srcp[base + l]);
                float2 hv = __ldg(&hin[s * 32 + lane]);
                float4 A = __ldg(&eap[(base + l) * 2]);
                float4 B = __ldg(&eap[(base + l) * 2 + 1]);
                float t0 = bc0 + hv.x, t1 = bc1 + hv.y;
                t0 = fmaf(A.x, wA[0], t0);  t1 = fmaf(A.x, wB[0], t1);
                t0 = fmaf(A.y, wA[1], t0);  t1 = fmaf(A.y, wB[1], t1);
                t0 = fmaf(A.z, wA[2], t0);  t1 = fmaf(A.z, wB[2], t1);
                t0 = fmaf(A.w, wA[3], t0);  t1 = fmaf(A.w, wB[3], t1);
                t0 = fmaf(B.x, wA[4], t0);  t1 = fmaf(B.x, wB[4], t1);
                t0 = fmaf(B.y, wA[5], t0);  t1 = fmaf(B.y, wB[5], t1);
                t0 = fmaf(B.z, wA[6], t0);  t1 = fmaf(B.z, wB[6], t1);
                t0 = fmaf(B.w, wA[7], t0);  t1 = fmaf(B.w, wB[7], t1);
                float v0 = fmaxf(t0, 0.f);
                float v1 = fmaxf(t1, 0.f);
                float ex0 = __expf(v0);
                float ex1 = __expf(v1);
                d0 += ex0;  n0 = fmaf(v0, ex0, n0);
                d1 += ex1;  n1 = fmaf(v1, ex1, n1);
            }

            float2 hme = __ldg(&hin[node * 32 + lane]);
            float a0 = hme.x + ((cnt > 0) ? (n0 / d0 + 1e-7f) : 0.f);
            float a1 = hme.y + ((cnt > 0) ? (n1 / d1 + 1e-7f) : 0.f);
            // MLP: y = a @ Wm + bm (64x64 warp shfl-GEMM, paired float2 LDS)
            float acc0 = bm0, acc1 = bm1;
            const float2* wm2 = (const float2*)wms;
            #pragma unroll
            for (int k = 0; k < 32; k++) {
                float2 w = wm2[k * 32 + lane];
                float v = __shfl_sync(0xffffffffu, a0, k);
                acc0 = fmaf(v, w.x, acc0);
                acc1 = fmaf(v, w.y, acc1);
            }
            #pragma unroll
            for (int k = 0; k < 32; k++) {
                float2 w = wm2[(k + 32) * 32 + lane];
                float v = __shfl_sync(0xffffffffu, a1, k);
                acc0 = fmaf(v, w.x, acc0);
                acc1 = fmaf(v, w.y, acc1);
            }
            float* o = g_h + node * 128 + outoff;
            float y0 = o[lane] + acc0, y1 = o[lane + 32] + acc1;
            o[lane] = y0;  o[lane + 32] = y1;
            if (hasnext) {
                float su = y0 + y1, q = y0 * y0 + y1 * y1;
                #pragma unroll
                for (int d = 16; d > 0; d >>= 1) {
                    su += __shfl_xor_sync(0xffffffffu, su, d);
                    q  += __shfl_xor_sync(0xffffffffu, q, d);
                }
                float mu = su * (1.f / 64.f);
                float rs = rsqrtf(q * (1.f / 64.f) - mu * mu + 1e-5f);
                float r0 = fmaxf((y0 - mu) * rs * g0 + nb0, 0.f);
                float r1 = fmaxf((y1 - mu) * rs * g1 + nb1, 0.f);
                hout[node * 32 + lane] = make_float2(r0, r1);
            } else {
                // last phase: reset degree for next replay (owner warp only)
                if (lane == 0) g_cnt[node] = 0;
            }
            __syncwarp();
        }
        if (phase < 3) {
            GRID_BARRIER(phase)
        }
    }
}

// ---------- final: out = relu(LN(h)) @ Wp + bp, ALL 112 cols, one launch -----
__global__ void k_final1(const float* __restrict__ lg, const float* __restrict__ lb,
                         const float* __restrict__ Wp, const float* __restrict__ bp,
                         float* __restrict__ out) {
    extern __shared__ float4 wp4[];     // 128*32 float4 = 64KB dynamic
    int tid = threadIdx.x;
    for (int i = tid; i < 4096; i += blockDim.x) {
        int k = i >> 5, c = i & 31;
        float w0 = Wp[k * 112 + c];
        float w1 = Wp[k * 112 + c + 32];
        float w2 = Wp[k * 112 + c + 64];
        float w3 = (c < 16) ? Wp[k * 112 + c + 96] : 0.f;
        wp4[i] = make_float4(w0, w1, w2, w3);
    }
    __syncthreads();
    int lane = tid & 31;
    int warp = blockIdx.x * (blockDim.x >> 5) + (tid >> 5);
    int nw = gridDim.x * (blockDim.x >> 5);
    bool has3 = lane < 16;
    float bp0 = bp[lane], bp1 = bp[lane + 32], bp2 = bp[lane + 64];
    float bp3 = has3 ? bp[lane + 96] : 0.f;
    float lgv[4], lbv[4];
    #pragma unroll
    for (int i = 0; i < 4; i++) { lgv[i] = lg[lane + i * 32]; lbv[i] = lb[lane + i * 32]; }
    for (int n = warp * 2; n < NN; n += nw * 2) {
        int n2 = n + 1;
        const float* hA = g_h + n * 128;
        const float* hB = g_h + n2 * 128;
        float xA[4], xB[4];
        #pragma unroll
        for (int i = 0; i < 4; i++) { xA[i] = hA[lane + i * 32]; xB[i] = hB[lane + i * 32]; }
        float sA = 0.f, qA = 0.f, sB = 0.f, qB = 0.f;
        #pragma unroll
        for (int i = 0; i < 4; i++) {
            sA += xA[i]; qA += xA[i] * xA[i];
            sB += xB[i]; qB += xB[i] * xB[i];
        }
        #pragma unroll
        for (int d = 16; d > 0; d >>= 1) {
            sA += __shfl_xor_sync(0xffffffffu, sA, d);
            qA += __shfl_xor_sync(0xffffffffu, qA, d);
            sB += __shfl_xor_sync(0xffffffffu, sB, d);
            qB += __shfl_xor_sync(0xffffffffu, qB, d);
        }
        float muA = sA * (1.f / 128.f), muB = sB * (1.f / 128.f);
        float rsA = rsqrtf(qA * (1.f / 128.f) - muA * muA + 1e-5f);
        float rsB = rsqrtf(qB * (1.f / 128.f) - muB * muB + 1e-5f);
        #pragma unroll
        for (int i = 0; i < 4; i++) {
            xA[i] = fmaxf((xA[i] - muA) * rsA * lgv[i] + lbv[i], 0.f);
            xB[i] = fmaxf((xB[i] - muB) * rsB * lgv[i] + lbv[i], 0.f);
        }
        float aA0 = bp0, aA1 = bp1, aA2 = bp2, aA3 = bp3;
        float aB0 = bp0, aB1 = bp1, aB2 = bp2, aB3 = bp3;
        #pragma unroll
        for (int i = 0; i < 4; i++) {
            #pragma unroll
            for (int k = 0; k < 32; k++) {
                float4 w = wp4[(k + i * 32) * 32 + lane];
                float vA = __shfl_sync(0xffffffffu, xA[i], k);
                float vB = __shfl_sync(0xffffffffu, xB[i], k);
                aA0 = fmaf(vA, w.x, aA0);  aA1 = fmaf(vA, w.y, aA1);
                aA2 = fmaf(vA, w.z, aA2);  aA3 = fmaf(vA, w.w, aA3);
                aB0 = fmaf(vB, w.x, aB0);  aB1 = fmaf(vB, w.y, aB1);
                aB2 = fmaf(vB, w.z, aB2);  aB3 = fmaf(vB, w.w, aB3);
            }
        }
        out[n * 112 + lane] = aA0;
        out[n * 112 + lane + 32] = aA1;
        out[n * 112 + lane + 64] = aA2;
        out[n2 * 112 + lane] = aB0;
        out[n2 * 112 + lane + 32] = aB1;
        out[n2 * 112 + lane + 64] = aB2;
        if (has3) {
            out[n * 112 + lane + 96] = aA3;
            out[n2 * 112 + lane + 96] = aB3;
        }
    }
}

// ---------------- launch ----------------------------------------------------
extern "C" void kernel_launch(void* const* d_in, const int* in_sizes, int n_in,
                              void* d_out, int out_size) {
    const float* x     = (const float*)d_in[0];
    const int*   nidx  = (const int*)d_in[1];
    const int*   ei    = (const int*)d_in[2];
    const float* ea    = (const float*)d_in[3];
    const float* nodef = (const float*)d_in[4];
    const float* Woh   = (const float*)d_in[5];
    const float* boh   = (const float*)d_in[6];
    const float* Wne   = (const float*)d_in[7];
    const float* bne   = (const float*)d_in[8];
    const float* Wee   = (const float*)d_in[9];
    const float* bee   = (const float*)d_in[10];
    const float* lng   = (const float*)d_in[11];
    const float* lnb   = (const float*)d_in[12];
    const float* We    = (const float*)d_in[13];
    const float* be    = (const float*)d_in[14];
    const float* Wm    = (const float*)d_in[15];
    const float* bm    = (const float*)d_in[16];
    const float* lastg = (const float*)d_in[17];
    const float* lastb = (const float*)d_in[18];
    const float* Wp    = (const float*)d_in[19];
    const float* bp    = (const float*)d_in[20];
    float* out = (float*)d_out;

    const int* src = ei;
    const int* dst = ei + EE;

    static int nsm = 0;
    if (nsm == 0) {
        int dev = 0;
        cudaGetDevice(&dev);
        cudaDeviceGetAttribute(&nsm, cudaDevAttrMultiProcessorCount, dev);
        cudaFuncSetAttribute(k_final1, cudaFuncAttributeMaxDynamicSharedMemorySize, 65536);
    }

    k_prep_all<<<nsm * 4, 256>>>(src, dst, (const float4*)ea,
                                 x, nidx, nodef, Woh, boh, Wne, bne,
                                 lng, lnb, Wee, bee, We, be);
    k_gen<<<nsm * 4, 256>>>(Wm, bm, lng, lnb);
    k_final1<<<nsm * 3, 256, 65536>>>(lastg, lastb, Wp, bp, out);
}